// round 2
// baseline (speedup 1.0000x reference)
#include <cuda_runtime.h>
#include <math.h>

// Problem constants
#define LAYERS 8
#define BATCH  256
#define TIME   8
#define EDIM   1024
#define HDIM   1024
#define KDIM   2048   // EDIM + HDIM

// Tiling
#define BM 128   // batch rows per block
#define BJ 16    // hidden columns per block (per gate; block computes 4 gates)
#define BK 16    // k-slice

// Scratch: ping-pong per-layer outputs (T,B,H) + running cell state (B,H)
__device__ float g_buf0[TIME * BATCH * HDIM];
__device__ float g_buf1[TIME * BATCH * HDIM];
__device__ float g_crun[BATCH * HDIM];

__global__ __launch_bounds__(256, 1)
void lstm_step_kernel(
    const float* __restrict__ inA, int strideA,      // input rows: (B x E), row stride strideA
    const float* __restrict__ hprev,                 // (B x H), row stride H
    const float* __restrict__ Wu, const float* __restrict__ Wf,
    const float* __restrict__ Wo, const float* __restrict__ Wc,  // each (K2 x H) row-major
    const float* __restrict__ bu, const float* __restrict__ bf,
    const float* __restrict__ bo, const float* __restrict__ bc,  // each (H)
    const float* __restrict__ c_old_src,             // c0[l] (t==0) or g_crun
    float* __restrict__ c_run,                       // (B x H)
    float* __restrict__ h_out,                       // cur[t] (B x H)
    float* __restrict__ outH,                        // base + t*H (stride T*H) or null
    float* __restrict__ outC,                        // base + t*H (stride T*H) or null
    float* __restrict__ outHt,                       // (B x H) or null
    float* __restrict__ outCt)                       // (B x H) or null
{
    __shared__ float zs[BK][BM];        // z tile [k][b]
    __shared__ float ws[4][BK][BJ];     // weights [gate][k][j]

    const int tid = threadIdx.x;
    const int tx = tid & 15;            // j within tile
    const int ty = tid >> 4;            // row group
    const int j0 = blockIdx.x * BJ;
    const int b0 = blockIdx.y * BM;

    float acc[4][8];
    #pragma unroll
    for (int g = 0; g < 4; g++)
        #pragma unroll
        for (int r = 0; r < 8; r++)
            acc[g][r] = 0.0f;

    #pragma unroll 1
    for (int k0 = 0; k0 < KDIM; k0 += BK) {
        // Load z tile: 128 rows x 16 k, thread (ty,tx) -> rows ty+16r, k=tx
        {
            const int gk = k0 + tx;
            if (gk < EDIM) {
                #pragma unroll
                for (int r = 0; r < 8; r++) {
                    const int b = b0 + ty + r * 16;
                    zs[tx][ty + r * 16] = inA[(size_t)b * strideA + gk];
                }
            } else {
                const int hk = gk - EDIM;
                #pragma unroll
                for (int r = 0; r < 8; r++) {
                    const int b = b0 + ty + r * 16;
                    zs[tx][ty + r * 16] = hprev[(size_t)b * HDIM + hk];
                }
            }
        }
        // Load weight tiles: 4 gates x 16 k x 16 j = 1024 floats, 4 per thread
        {
            #pragma unroll
            for (int i = 0; i < 4; i++) {
                const int e  = tid + i * 256;
                const int g  = e >> 8;
                const int kk = (e >> 4) & 15;
                const int jj = e & 15;
                const float* W = (g == 0) ? Wu : (g == 1) ? Wf : (g == 2) ? Wo : Wc;
                ws[g][kk][jj] = W[(size_t)(k0 + kk) * HDIM + (j0 + jj)];
            }
        }
        __syncthreads();

        #pragma unroll
        for (int kk = 0; kk < BK; kk++) {
            const float w0 = ws[0][kk][tx];
            const float w1 = ws[1][kk][tx];
            const float w2 = ws[2][kk][tx];
            const float w3 = ws[3][kk][tx];
            #pragma unroll
            for (int r = 0; r < 8; r++) {
                const float z = zs[kk][ty + r * 16];
                acc[0][r] = fmaf(z, w0, acc[0][r]);
                acc[1][r] = fmaf(z, w1, acc[1][r]);
                acc[2][r] = fmaf(z, w2, acc[2][r]);
                acc[3][r] = fmaf(z, w3, acc[3][r]);
            }
        }
        __syncthreads();
    }

    // Epilogue: LSTM cell update, fused
    const int j = j0 + tx;
    const float b_u = bu[j], b_f = bf[j], b_o = bo[j], b_c = bc[j];

    #pragma unroll
    for (int r = 0; r < 8; r++) {
        const int b = b0 + ty + r * 16;
        const size_t idx = (size_t)b * HDIM + j;
        const float u  = 1.0f / (1.0f + expf(-(acc[0][r] + b_u)));
        const float f  = 1.0f / (1.0f + expf(-(acc[1][r] + b_f)));
        const float o  = 1.0f / (1.0f + expf(-(acc[2][r] + b_o)));
        const float ct = tanhf(acc[3][r] + b_c);
        const float c_old = c_old_src[idx];
        const float c_new = f * c_old + u * ct;
        const float h_new = o * tanhf(c_new);
        c_run[idx] = c_new;
        h_out[idx] = h_new;
        if (outH) {
            const size_t oidx = (size_t)b * (TIME * HDIM) + j;  // outH already offset by t*H
            outH[oidx] = h_new;
            outC[oidx] = c_new;
            if (outHt) {
                outHt[idx] = h_new;
                outCt[idx] = c_new;
            }
        }
    }
}

extern "C" void kernel_launch(void* const* d_in, const int* in_sizes, int n_in,
                              void* d_out, int out_size) {
    const float* x  = (const float*)d_in[0];   // (B, T, E)
    const float* h0 = (const float*)d_in[1];   // (L, B, H)
    const float* c0 = (const float*)d_in[2];   // (L, B, H)
    const float* Wu = (const float*)d_in[3];   // (L, K2, H)
    const float* bu = (const float*)d_in[4];   // (L, H)
    const float* Wf = (const float*)d_in[5];
    const float* bf = (const float*)d_in[6];
    const float* Wo = (const float*)d_in[7];
    const float* bo = (const float*)d_in[8];
    const float* Wc = (const float*)d_in[9];
    const float* bc = (const float*)d_in[10];

    float* out = (float*)d_out;
    float* outHidden = out;                                        // (B, T, H)
    float* outMem    = out + (size_t)BATCH * TIME * HDIM;          // (B, T, H)
    float* outHt     = out + (size_t)2 * BATCH * TIME * HDIM;      // (B, 1, H)
    float* outCt     = outHt + (size_t)BATCH * HDIM;               // (B, 1, H)

    float *buf0, *buf1, *crun;
    cudaGetSymbolAddress((void**)&buf0, g_buf0);
    cudaGetSymbolAddress((void**)&buf1, g_buf1);
    cudaGetSymbolAddress((void**)&crun, g_crun);

    const dim3 grid(HDIM / BJ, BATCH / BM);  // (64, 2)
    const dim3 block(256);

    // Layer-outer, time-inner: keeps one layer's 32 MB of weights L2-resident
    // across all 8 timesteps.
    for (int l = 0; l < LAYERS; l++) {
        const size_t wOff = (size_t)l * KDIM * HDIM;
        const size_t bOff = (size_t)l * HDIM;
        const float* Wu_l = Wu + wOff;
        const float* Wf_l = Wf + wOff;
        const float* Wo_l = Wo + wOff;
        const float* Wc_l = Wc + wOff;
        const float* bu_l = bu + bOff;
        const float* bf_l = bf + bOff;
        const float* bo_l = bo + bOff;
        const float* bc_l = bc + bOff;

        float* cur        = (l & 1) ? buf1 : buf0;
        const float* prev = (l & 1) ? buf0 : buf1;
        const bool last = (l == LAYERS - 1);

        for (int t = 0; t < TIME; t++) {
            const float* inA;
            int strideA;
            if (l == 0) {
                inA = x + (size_t)t * EDIM;      // x[b][t][:] with row stride T*E
                strideA = TIME * EDIM;
            } else {
                inA = prev + (size_t)t * BATCH * HDIM;
                strideA = HDIM;
            }
            const float* hprev = (t == 0) ? (h0 + (size_t)l * BATCH * HDIM)
                                          : (cur + (size_t)(t - 1) * BATCH * HDIM);
            const float* coldsrc = (t == 0) ? (c0 + (size_t)l * BATCH * HDIM) : crun;
            float* hout = cur + (size_t)t * BATCH * HDIM;

            float* oH  = last ? (outHidden + (size_t)t * HDIM) : nullptr;
            float* oC  = last ? (outMem + (size_t)t * HDIM) : nullptr;
            float* oHt = (last && t == TIME - 1) ? outHt : nullptr;
            float* oCt = (last && t == TIME - 1) ? outCt : nullptr;

            lstm_step_kernel<<<grid, block>>>(
                inA, strideA, hprev,
                Wu_l, Wf_l, Wo_l, Wc_l,
                bu_l, bf_l, bo_l, bc_l,
                coldsrc, crun, hout,
                oH, oC, oHt, oCt);
        }
    }
}